// round 1
// baseline (speedup 1.0000x reference)
#include <cuda_runtime.h>

// ---------------------------------------------------------------------------
// Problem constants
// ---------------------------------------------------------------------------
#define T0 4096
#define T1 8192
#define BATCH 8
#define KSZ 15
#define PADSZ 7
#define NJ 27

// Scratch (device globals; allocation is forbidden)
__device__ float g_bufA[BATCH * 270 * T1];   // 70.8 MB
__device__ float g_bufB[BATCH * 270 * T1];   // 70.8 MB
__device__ float g_gi[BATCH * 162 * T1];     // 42.5 MB

// ---------------------------------------------------------------------------
// Skeleton adjacency (output joint -> input joints), traced from the Python
// _get_neighbors() including contact-virtual-joint aliasing and root node.
// ---------------------------------------------------------------------------
__constant__ int c_nb_cnt[NJ] = {
    8, 7, 6, 5, 4, 7, 6, 5, 4, 7, 8, 9, 6, 3, 7, 5, 4, 3, 7, 5, 4, 3, 6, 5, 6, 5, 12
};
__constant__ int c_nb[NJ][12] = {
    {0, 1, 2, 5, 6, 9, 10, 26, 0, 0, 0, 0},             // 0
    {0, 1, 2, 3, 5, 9, 26, 0, 0, 0, 0, 0},              // 1
    {0, 1, 2, 3, 4, 26, 0, 0, 0, 0, 0, 0},              // 2
    {1, 2, 3, 4, 22, 0, 0, 0, 0, 0, 0, 0},              // 3
    {2, 3, 4, 23, 0, 0, 0, 0, 0, 0, 0, 0},              // 4
    {0, 1, 5, 6, 7, 9, 26, 0, 0, 0, 0, 0},              // 5
    {0, 5, 6, 7, 8, 26, 0, 0, 0, 0, 0, 0},              // 6
    {5, 6, 7, 8, 24, 0, 0, 0, 0, 0, 0, 0},              // 7
    {6, 7, 8, 25, 0, 0, 0, 0, 0, 0, 0, 0},              // 8
    {0, 1, 5, 9, 10, 11, 26, 0, 0, 0, 0, 0},            // 9
    {0, 9, 10, 11, 12, 14, 18, 26, 0, 0, 0, 0},         // 10
    {9, 10, 11, 12, 13, 14, 15, 18, 19, 0, 0, 0},       // 11
    {10, 11, 12, 13, 14, 18, 0, 0, 0, 0, 0, 0},         // 12
    {11, 12, 13, 0, 0, 0, 0, 0, 0, 0, 0, 0},            // 13
    {10, 11, 12, 14, 15, 16, 18, 0, 0, 0, 0, 0},        // 14
    {11, 14, 15, 16, 17, 0, 0, 0, 0, 0, 0, 0},          // 15
    {14, 15, 16, 17, 0, 0, 0, 0, 0, 0, 0, 0},           // 16
    {15, 16, 17, 0, 0, 0, 0, 0, 0, 0, 0, 0},            // 17
    {10, 11, 12, 14, 18, 19, 20, 0, 0, 0, 0, 0},        // 18
    {11, 18, 19, 20, 21, 0, 0, 0, 0, 0, 0, 0},          // 19
    {18, 19, 20, 21, 0, 0, 0, 0, 0, 0, 0, 0},           // 20
    {19, 20, 21, 0, 0, 0, 0, 0, 0, 0, 0, 0},            // 21
    {1, 2, 3, 4, 22, 26, 0, 0, 0, 0, 0, 0},             // 22
    {2, 3, 4, 23, 26, 0, 0, 0, 0, 0, 0, 0},             // 23
    {5, 6, 7, 8, 24, 26, 0, 0, 0, 0, 0, 0},             // 24
    {6, 7, 8, 25, 26, 0, 0, 0, 0, 0, 0, 0},             // 25
    {0, 1, 2, 5, 6, 9, 10, 22, 23, 24, 25, 26}          // 26
};

// ---------------------------------------------------------------------------
// Skeleton conv kernel.
//   grid  = (T/512, 27, BATCH)
//   block = (32, CO_PJ)    each thread: 16 timesteps x 1 output channel
// Shared x tile uses a pad-4-floats-per-32 layout so stride-64B float4 LDS
// is 4-phase conflict-free.
// ---------------------------------------------------------------------------
template <int CI_PJ, int CO_PJ, bool ADD_IN, bool ADD_RES, bool LRELU>
__global__ void sconv_kernel(const float* __restrict__ x,
                             const float* __restrict__ x2,   // added to x if ADD_IN
                             const float* __restrict__ w,
                             const float* __restrict__ bias,
                             const float* __restrict__ res,  // added to out if ADD_RES
                             float* __restrict__ y,
                             int T)
{
    constexpr int CIN  = CI_PJ * NJ;
    constexpr int COUT = CO_PJ * NJ;
    constexpr int TT   = 512;
    constexpr int TPT  = 16;
    constexpr int LROW = TT + 2 * PADSZ;          // 526 logical floats per ci row
    constexpr int PROW = 592;                     // padded physical row (>= 525+4*16+1)
    constexpr int NT   = 32 * CO_PJ;

    __shared__ __align__(16) float sx[CI_PJ * PROW];
    __shared__ __align__(16) float sw[CO_PJ * CI_PJ * 16];

    const int b   = blockIdx.z;
    const int j   = blockIdx.y;
    const int t0  = blockIdx.x * TT;
    const int tx  = threadIdx.x;
    const int col = threadIdx.y;
    const int tid = col * 32 + tx;
    const int t_local = tx * TPT;

    float acc[TPT];
#pragma unroll
    for (int i = 0; i < TPT; ++i) acc[i] = 0.0f;

    const int cnt = c_nb_cnt[j];
    for (int ji = 0; ji < cnt; ++ji) {
        const int jn = c_nb[j][ji];
        __syncthreads();  // protect previous iteration's smem reads

        // ---- stage x tile for input joint jn (with reflect padding) ----
        const float* xbase  = x + ((size_t)b * CIN + jn * CI_PJ) * (size_t)T;
        const float* x2base = ADD_IN ? x2 + ((size_t)b * CIN + jn * CI_PJ) * (size_t)T
                                     : nullptr;
        for (int idx = tid; idx < CI_PJ * LROW; idx += NT) {
            int ci = idx / LROW;
            int p  = idx - ci * LROW;
            int g  = t0 - PADSZ + p;
            if (g < 0) g = -g;
            else if (g >= T) g = 2 * T - 2 - g;
            float v = xbase[ci * T + g];
            if (ADD_IN) v += x2base[ci * T + g];
            sx[ci * PROW + p + 4 * (p >> 5)] = v;
        }

        // ---- stage weight block (co x ci x 15, row padded to 16) ----
        const float* wbase = w + ((size_t)(j * CO_PJ) * CIN + jn * CI_PJ) * KSZ;
        for (int idx = tid; idx < CO_PJ * CI_PJ * KSZ; idx += NT) {
            int co = idx / (CI_PJ * KSZ);
            int r  = idx - co * CI_PJ * KSZ;
            int ci = r / KSZ;
            int k  = r - ci * KSZ;
            sw[(co * CI_PJ + ci) * 16 + k] = wbase[(co * CIN + ci) * KSZ + k];
        }
        __syncthreads();

        // ---- accumulate ----
#pragma unroll
        for (int ci = 0; ci < CI_PJ; ++ci) {
            float wv[16];
            {
                const float4* wp = (const float4*)&sw[(col * CI_PJ + ci) * 16];
#pragma unroll
                for (int q = 0; q < 4; ++q) ((float4*)wv)[q] = wp[q];
            }
            float xv[32];
            {
                const float* xrow = &sx[ci * PROW];
#pragma unroll
                for (int c = 0; c < 8; ++c) {
                    int lg = t_local + 4 * c;
                    int ph = lg + 4 * (lg >> 5);
                    ((float4*)xv)[c] = *(const float4*)(xrow + ph);
                }
            }
#pragma unroll
            for (int tt = 0; tt < TPT; ++tt) {
#pragma unroll
                for (int k = 0; k < KSZ; ++k) {
                    acc[tt] = fmaf(wv[k], xv[tt + k], acc[tt]);
                }
            }
        }
    }

    // ---- epilogue: bias, LeakyReLU, residual, store ----
    const int cg = j * CO_PJ + col;
    const float bv = bias[cg];
    float outv[TPT];
#pragma unroll
    for (int tt = 0; tt < TPT; ++tt) {
        float v = acc[tt] + bv;
        if (LRELU) v = (v > 0.0f) ? v : 0.2f * v;
        outv[tt] = v;
    }
    const size_t obase = ((size_t)b * COUT + cg) * (size_t)T + t0 + t_local;
    if (ADD_RES) {
#pragma unroll
        for (int q = 0; q < 4; ++q) {
            float4 r4 = *(const float4*)(res + obase + 4 * q);
            outv[4 * q + 0] += r4.x;
            outv[4 * q + 1] += r4.y;
            outv[4 * q + 2] += r4.z;
            outv[4 * q + 3] += r4.w;
        }
    }
#pragma unroll
    for (int q = 0; q < 4; ++q) {
        *(float4*)(y + obase + 4 * q) =
            make_float4(outv[4 * q + 0], outv[4 * q + 1], outv[4 * q + 2], outv[4 * q + 3]);
    }
}

// ---------------------------------------------------------------------------
// Linear interpolation (torch F.interpolate, mode='linear', align_corners=False)
// ---------------------------------------------------------------------------
__global__ void interp_kernel(const float* __restrict__ in, float* __restrict__ out,
                              int Tin, int Tout, int BC)
{
    int idx = blockIdx.x * blockDim.x + threadIdx.x;
    if (idx >= BC * Tout) return;
    int t  = idx % Tout;
    int bc = idx / Tout;
    float scale = (float)Tin / (float)Tout;
    float src = ((float)t + 0.5f) * scale - 0.5f;
    src = fminf(fmaxf(src, 0.0f), (float)(Tin - 1));
    int i0 = (int)floorf(src);
    int i1 = min(i0 + 1, Tin - 1);
    float wgt = src - (float)i0;
    const float* row = in + (size_t)bc * Tin;
    out[idx] = row[i0] * (1.0f - wgt) + row[i1] * wgt;
}

// ---------------------------------------------------------------------------
// Launch
// ---------------------------------------------------------------------------
extern "C" void kernel_launch(void* const* d_in, const int* in_sizes, int n_in,
                              void* d_out, int out_size)
{
    (void)in_sizes; (void)n_in; (void)out_size;

    const float* noise0    = (const float*)d_in[0];
    const float* generated = (const float*)d_in[1];
    const float* noise1    = (const float*)d_in[2];

    const float* W[2][4];
    const float* Bv[2][4];
    int idx = 3;
    for (int s = 0; s < 2; ++s) {
        for (int l = 0; l < 4; ++l) {
            W[s][l]  = (const float*)d_in[idx++];
            Bv[s][l] = (const float*)d_in[idx++];
        }
    }

    float *bufA, *bufB, *gi;
    cudaGetSymbolAddress((void**)&bufA, g_bufA);
    cudaGetSymbolAddress((void**)&bufB, g_bufB);
    cudaGetSymbolAddress((void**)&gi, g_gi);

    float* g0 = (float*)d_out;
    float* g1 = g0 + (size_t)BATCH * 162 * T0;

    // ---------------- stage 0 (T = 4096) ----------------
    {
        dim3 grid(T0 / 512, NJ, BATCH);
        sconv_kernel<6, 5, true, false, true><<<grid, dim3(32, 5)>>>(
            generated, noise0, W[0][0], Bv[0][0], nullptr, bufA, T0);
        sconv_kernel<5, 10, false, false, true><<<grid, dim3(32, 10)>>>(
            bufA, nullptr, W[0][1], Bv[0][1], nullptr, bufB, T0);
        sconv_kernel<10, 10, false, false, true><<<grid, dim3(32, 10)>>>(
            bufB, nullptr, W[0][2], Bv[0][2], nullptr, bufA, T0);
        sconv_kernel<10, 6, false, true, false><<<grid, dim3(32, 6)>>>(
            bufA, nullptr, W[0][3], Bv[0][3], generated, g0, T0);
    }

    // ---------------- upsample g0 -> gi (T = 8192) ----------------
    {
        int n = BATCH * 162 * T1;
        interp_kernel<<<(n + 255) / 256, 256>>>(g0, gi, T0, T1, BATCH * 162);
    }

    // ---------------- stage 1 (T = 8192) ----------------
    {
        dim3 grid(T1 / 512, NJ, BATCH);
        sconv_kernel<6, 5, true, false, true><<<grid, dim3(32, 5)>>>(
            gi, noise1, W[1][0], Bv[1][0], nullptr, bufA, T1);
        sconv_kernel<5, 10, false, false, true><<<grid, dim3(32, 10)>>>(
            bufA, nullptr, W[1][1], Bv[1][1], nullptr, bufB, T1);
        sconv_kernel<10, 10, false, false, true><<<grid, dim3(32, 10)>>>(
            bufB, nullptr, W[1][2], Bv[1][2], nullptr, bufA, T1);
        sconv_kernel<10, 6, false, true, false><<<grid, dim3(32, 6)>>>(
            bufA, nullptr, W[1][3], Bv[1][3], gi, g1, T1);
    }
}